// round 6
// baseline (speedup 1.0000x reference)
#include <cuda_runtime.h>
#include <cuda_bf16.h>
#include <cstdint>
#include <cstddef>

// ---------------- problem dims ----------------
#define B_   128
#define S_   256
#define D_   256
#define H_   6
#define HS_  42
#define DFF_ 1024
#define BS_  (B_ * S_)     // 32768
#define QKVP 768           // padded 3*H*HS (756 -> 768)
#define HCN  252           // H*HS

// ---------------- scratch (device globals) ----------------
__device__ float          g_qkv [(size_t)BS_ * QKVP];
__device__ __nv_bfloat16  g_xs_h[(size_t)BS_ * D_];
__device__ __nv_bfloat16  g_xs_l[(size_t)BS_ * D_];
__device__ __nv_bfloat16  g_hc_h[(size_t)BS_ * 256];
__device__ __nv_bfloat16  g_hc_l[(size_t)BS_ * 256];
__device__ float          g_y1  [(size_t)BS_ * D_];
__device__ float          g_ln1 [(size_t)BS_ * D_];
__device__ __nv_bfloat16  g_l1_h[(size_t)BS_ * D_];
__device__ __nv_bfloat16  g_l1_l[(size_t)BS_ * D_];
__device__ __nv_bfloat16  g_ff_h[(size_t)BS_ * DFF_];
__device__ __nv_bfloat16  g_ff_l[(size_t)BS_ * DFF_];
__device__ float          g_y2  [(size_t)BS_ * D_];
__device__ __nv_bfloat16  g_wqkv_h[QKVP * D_],  g_wqkv_l[QKVP * D_];
__device__ __nv_bfloat16  g_wpj_h [D_ * 256],   g_wpj_l [D_ * 256];
__device__ __nv_bfloat16  g_w1_h  [DFF_ * D_],  g_w1_l  [DFF_ * D_];
__device__ __nv_bfloat16  g_w2_h  [D_ * DFF_],  g_w2_l  [D_ * DFF_];

// ---------------- helpers ----------------
__device__ __forceinline__ void split2(float v, __nv_bfloat16& h, __nv_bfloat16& l) {
    h = __float2bfloat16_rn(v);
    l = __float2bfloat16_rn(v - __bfloat162float(h));
}
__device__ __forceinline__ uint32_t smem_u32(const void* p) {
    uint32_t a;
    asm("{ .reg .u64 t; cvta.to.shared.u64 t, %1; cvt.u32.u64 %0, t; }" : "=r"(a) : "l"(p));
    return a;
}
__device__ __forceinline__ void cp16(uint32_t sdst, const void* g) {
    asm volatile("cp.async.cg.shared.global [%0], [%1], 16;" :: "r"(sdst), "l"(g));
}
#define LDSM4(r0, r1, r2, r3, a) \
    asm volatile("ldmatrix.sync.aligned.m8n8.x4.shared.b16 {%0,%1,%2,%3}, [%4];" \
                 : "=r"(r0), "=r"(r1), "=r"(r2), "=r"(r3) : "r"(a))
#define MMA16816(d, a, b) \
    asm volatile("mma.sync.aligned.m16n8k16.row.col.f32.bf16.bf16.f32 " \
                 "{%0,%1,%2,%3},{%4,%5,%6,%7},{%8,%9},{%0,%1,%2,%3};" \
                 : "+f"((d)[0]), "+f"((d)[1]), "+f"((d)[2]), "+f"((d)[3]) \
                 : "r"((a)[0]), "r"((a)[1]), "r"((a)[2]), "r"((a)[3]), \
                   "r"((b)[0]), "r"((b)[1]))

// ---------------- merged conversion kernel ----------------
// job ranges (element index space)
#define CE1 (BS_ * D_)                 // x split            8388608
#define CE2 (CE1 + QKVP * D_)          // wqkv transpose+split
#define CE3 (CE2 + D_ * 256)           // wproj t+split (Kp=256)
#define CE4 (CE3 + DFF_ * D_)          // w1 t+split
#define CE5 (CE4 + D_ * DFF_)          // w2 t+split
__global__ void conv_kernel(const float* __restrict__ x,
                            const float* __restrict__ Wq, const float* __restrict__ Wk,
                            const float* __restrict__ Wv, const float* __restrict__ Wproj,
                            const float* __restrict__ W1, const float* __restrict__ W2,
                            __nv_bfloat16* __restrict__ xs_h, __nv_bfloat16* __restrict__ xs_l,
                            __nv_bfloat16* __restrict__ wqkv_h, __nv_bfloat16* __restrict__ wqkv_l,
                            __nv_bfloat16* __restrict__ wpj_h, __nv_bfloat16* __restrict__ wpj_l,
                            __nv_bfloat16* __restrict__ w1_h, __nv_bfloat16* __restrict__ w1_l,
                            __nv_bfloat16* __restrict__ w2_h, __nv_bfloat16* __restrict__ w2_l) {
    int idx = blockIdx.x * 256 + threadIdx.x;
    if (idx < CE1) {
        split2(x[idx], xs_h[idx], xs_l[idx]);
    } else if (idx < CE2) {
        int i = idx - CE1;
        int n = i / D_, k = i % D_;
        float v = 0.f;
        if (n < 756) {
            int which = n / HCN, r = n % HCN, h = r / HS_, e = r % HS_;
            const float* W = (which == 0) ? Wq : (which == 1) ? Wk : Wv;
            v = W[((size_t)h * D_ + k) * HS_ + e];
        }
        split2(v, wqkv_h[i], wqkv_l[i]);
    } else if (idx < CE3) {
        int i = idx - CE2;
        int n = i / 256, k = i % 256;
        float v = (k < HCN) ? Wproj[(size_t)k * D_ + n] : 0.f;
        split2(v, wpj_h[i], wpj_l[i]);
    } else if (idx < CE4) {
        int i = idx - CE3;
        int n = i / D_, k = i % D_;
        float v = W1[(size_t)k * DFF_ + n];
        split2(v, w1_h[i], w1_l[i]);
    } else if (idx < CE5) {
        int i = idx - CE4;
        int n = i / DFF_, k = i % DFF_;
        float v = W2[(size_t)k * D_ + n];
        split2(v, w2_h[i], w2_l[i]);
    }
}

// ---------------- fused 3-product mma.sync GEMM, 4-stage pipeline ----------------
// C[M,N] = (Ah+Al)[M,K] @ (Bh+Bl)^T[N,K] dropping Al*Bl.
// 16-wide k-slabs; per row (64B): [hi 32B | lo 32B], XOR-swizzled.
// EPI 0: Cf = v    EPI 1: Cf = v + bias[col] + res[row,col]
// EPI 3: split(relu(v + bias[col])) -> Ch/Cl planes
#define STG_BYTES 16384       // A 8KB + B 8KB per 16-k slab
template<int EPI>
__global__ __launch_bounds__(256, 2)
void mma_gemm(const __nv_bfloat16* __restrict__ Ah, const __nv_bfloat16* __restrict__ Al,
              const __nv_bfloat16* __restrict__ Bh, const __nv_bfloat16* __restrict__ Bl,
              const float* __restrict__ bias, const float* __restrict__ res,
              float* __restrict__ Cf, __nv_bfloat16* __restrict__ Ch,
              __nv_bfloat16* __restrict__ Cl, int M, int N, int K) {
    extern __shared__ char smem[];
    const uint32_t sbase = smem_u32(smem);
    const uint32_t DATA = (sbase + 1023) & ~1023u;
    const int tid = threadIdx.x, lane = tid & 31, wid = tid >> 5;
    const int wm = (wid & 1) * 64;      // warp m-offset
    const int wn = (wid >> 1) * 32;     // warp n-offset
    const int m0 = blockIdx.y * 128, n0 = blockIdx.x * 128;
    const int S = K / 16;               // 16-wide k-slabs

    float acc[4][4][4];
    #pragma unroll
    for (int i = 0; i < 4; i++)
        #pragma unroll
        for (int j = 0; j < 4; j++)
            #pragma unroll
            for (int r = 0; r < 4; r++) acc[i][j][r] = 0.f;

    // cp.async mapping: per operand 512 16B-chunks (128 rows x 4), 2 per thread.
    // chunk cc<2 -> hi plane (k cols cc*8); cc>=2 -> lo plane (k cols (cc-2)*8)
    int crow[2], csw[2], chi[2], ccol[2];
    #pragma unroll
    for (int i = 0; i < 2; i++) {
        int c = tid * 2 + i;
        int r = c >> 2, cc = c & 3;
        crow[i] = r;
        chi[i] = (cc < 2);
        ccol[i] = (cc & 1) * 8;
        csw[i] = r * 64 + ((cc * 16) ^ (((r >> 1) & 3) * 16));
    }

    auto load_slab = [&](int s, int stage) {
        int k0 = s * 16;
        uint32_t ab = DATA + stage * STG_BYTES;
        uint32_t bb = ab + 8192;
        #pragma unroll
        for (int i = 0; i < 2; i++) {
            const __nv_bfloat16* src = chi[i] ? Ah : Al;
            cp16(ab + csw[i], src + (size_t)(m0 + crow[i]) * K + k0 + ccol[i]);
        }
        #pragma unroll
        for (int i = 0; i < 2; i++) {
            const __nv_bfloat16* src = chi[i] ? Bh : Bl;
            cp16(bb + csw[i], src + (size_t)(n0 + crow[i]) * K + k0 + ccol[i]);
        }
        asm volatile("cp.async.commit_group;");
    };

    // per-lane ldmatrix fragment mapping
    const int lg = lane >> 3, l8 = lane & 7;
    const int a_r = (lg & 1) * 8 + l8;
    const int a_bc = ((lg >> 1) * 8) * 2;       // 0 or 16 bytes (hi plane)
    const int b_r = ((lg >> 1) & 1) * 8 + l8;
    const int b_bc = ((lg & 1) * 8) * 2;

    load_slab(0, 0);
    load_slab(1, 1);
    load_slab(2, 2);

    for (int s = 0; s < S; s++) {
        int rem = S - 1 - s;
        if (rem >= 2)      asm volatile("cp.async.wait_group 2;");
        else if (rem == 1) asm volatile("cp.async.wait_group 1;");
        else               asm volatile("cp.async.wait_group 0;");
        __syncthreads();
        if (s + 3 < S) load_slab(s + 3, (s + 3) & 3);

        const uint32_t ab = DATA + (s & 3) * STG_BYTES;
        const uint32_t bb = ab + 8192;

        uint32_t afr[4][4];
        // Ah fragments
        #pragma unroll
        for (int mf = 0; mf < 4; mf++) {
            int r = wm + mf * 16 + a_r;
            uint32_t addr = ab + r * 64 + (a_bc ^ (((r >> 1) & 3) * 16));
            LDSM4(afr[mf][0], afr[mf][1], afr[mf][2], afr[mf][3], addr);
        }
        // Bh + Bl fragments
        uint32_t bh[4][2], bl[4][2];
        #pragma unroll
        for (int nb = 0; nb < 2; nb++) {
            int r = wn + nb * 16 + b_r;
            int sx = ((r >> 1) & 3) * 16;
            uint32_t addr_h = bb + r * 64 + (b_bc ^ sx);
            uint32_t addr_l = bb + r * 64 + ((b_bc + 32) ^ sx);
            uint32_t r0, r1, r2, r3;
            LDSM4(r0, r1, r2, r3, addr_h);
            bh[nb * 2][0] = r0; bh[nb * 2][1] = r1;
            bh[nb * 2 + 1][0] = r2; bh[nb * 2 + 1][1] = r3;
            LDSM4(r0, r1, r2, r3, addr_l);
            bl[nb * 2][0] = r0; bl[nb * 2][1] = r1;
            bl[nb * 2 + 1][0] = r2; bl[nb * 2 + 1][1] = r3;
        }
        // Ah*Bh and Ah*Bl
        #pragma unroll
        for (int mf = 0; mf < 4; mf++)
            #pragma unroll
            for (int nf = 0; nf < 4; nf++)
                MMA16816(acc[mf][nf], afr[mf], bh[nf]);
        #pragma unroll
        for (int mf = 0; mf < 4; mf++)
            #pragma unroll
            for (int nf = 0; nf < 4; nf++)
                MMA16816(acc[mf][nf], afr[mf], bl[nf]);
        // Al fragments (reuse afr), then Al*Bh
        #pragma unroll
        for (int mf = 0; mf < 4; mf++) {
            int r = wm + mf * 16 + a_r;
            uint32_t addr = ab + r * 64 + ((a_bc + 32) ^ (((r >> 1) & 3) * 16));
            LDSM4(afr[mf][0], afr[mf][1], afr[mf][2], afr[mf][3], addr);
        }
        #pragma unroll
        for (int mf = 0; mf < 4; mf++)
            #pragma unroll
            for (int nf = 0; nf < 4; nf++)
                MMA16816(acc[mf][nf], afr[mf], bh[nf]);
    }

    // ---- epilogue: write accumulators directly ----
    const int qrow = lane >> 2, qcol = (lane & 3) * 2;
    #pragma unroll
    for (int mf = 0; mf < 4; mf++) {
        #pragma unroll
        for (int nf = 0; nf < 4; nf++) {
            int row0 = m0 + wm + mf * 16 + qrow;
            int col  = n0 + wn + nf * 8 + qcol;
            float* d = acc[mf][nf];
            #pragma unroll
            for (int half = 0; half < 2; half++) {
                int row = row0 + half * 8;
                float v0 = d[half * 2], v1 = d[half * 2 + 1];
                size_t go = (size_t)row * N + col;
                if (EPI == 0) {
                    *(float2*)&Cf[go] = make_float2(v0, v1);
                } else if (EPI == 1) {
                    float2 r2 = *(const float2*)&res[go];
                    float2 b2 = *(const float2*)&bias[col];
                    *(float2*)&Cf[go] = make_float2(v0 + b2.x + r2.x, v1 + b2.y + r2.y);
                } else {
                    float2 b2 = *(const float2*)&bias[col];
                    v0 = fmaxf(v0 + b2.x, 0.f);
                    v1 = fmaxf(v1 + b2.y, 0.f);
                    __nv_bfloat16 h0, l0, h1, l1;
                    split2(v0, h0, l0); split2(v1, h1, l1);
                    *(__nv_bfloat162*)&Ch[go] = __nv_bfloat162(h0, h1);
                    *(__nv_bfloat162*)&Cl[go] = __nv_bfloat162(l0, l1);
                }
            }
        }
    }
}

// ---------------- causal attention (qkv fp32 stride 768) -> split hc planes ----------------
__global__ void attn_kernel(const float* __restrict__ qkv,
                            __nv_bfloat16* __restrict__ hch, __nv_bfloat16* __restrict__ hcl) {
    extern __shared__ float sm[];
    float* Ks = sm;
    float* Vs = sm + S_ * HS_;
    int bh = blockIdx.x;
    int b = bh / H_, h = bh % H_;
    int tid = threadIdx.x;
    const size_t rowbase = (size_t)b * S_ * QKVP;

    for (int idx = tid; idx < S_ * HS_; idx += 256) {
        int t = idx / HS_, e = idx - t * HS_;
        size_t g = rowbase + (size_t)t * QKVP + h * HS_ + e;
        Ks[idx] = qkv[g + HCN];
        Vs[idx] = qkv[g + 2 * HCN];
    }
    __syncthreads();

    int s = tid;
    float q[HS_];
    {
        size_t g = rowbase + (size_t)s * QKVP + h * HS_;
        #pragma unroll
        for (int e = 0; e < HS_; e++) q[e] = qkv[g + e];
    }
    const float scale = rsqrtf((float)HS_);
    float m = -1e30f, l = 0.f;
    float o[HS_];
    #pragma unroll
    for (int e = 0; e < HS_; e++) o[e] = 0.f;

    for (int t = 0; t <= s; t++) {
        const float* kr = &Ks[t * HS_];
        float dot = 0.f;
        #pragma unroll
        for (int e = 0; e < HS_; e++) dot = fmaf(q[e], kr[e], dot);
        float p = dot * scale;
        float nm = fmaxf(m, p);
        float f = __expf(m - nm);
        float w = __expf(p - nm);
        l = l * f + w;
        const float* vr = &Vs[t * HS_];
        #pragma unroll
        for (int e = 0; e < HS_; e++) o[e] = fmaf(o[e], f, w * vr[e]);
        m = nm;
    }
    float inv = 1.f / l;
    size_t og = ((size_t)b * S_ + s) * 256 + h * HS_;
    #pragma unroll
    for (int e = 0; e < HS_; e++) {
        __nv_bfloat16 hh, ll;
        split2(o[e] * inv, hh, ll);
        hch[og + e] = hh; hcl[og + e] = ll;
    }
    if (h == 0) {
        size_t pg = ((size_t)b * S_ + s) * 256 + 252;
        #pragma unroll
        for (int e = 0; e < 4; e++) { hch[pg + e] = __nv_bfloat16(0.f); hcl[pg + e] = __nv_bfloat16(0.f); }
    }
}

// ---------------- LayerNorm (optional split-plane outputs) ----------------
__global__ void ln_kernel(const float* __restrict__ in, const float* __restrict__ gam,
                          const float* __restrict__ bet, float* __restrict__ out,
                          __nv_bfloat16* __restrict__ oh, __nv_bfloat16* __restrict__ ol) {
    int warp = threadIdx.x >> 5, lane = threadIdx.x & 31;
    size_t row = (size_t)blockIdx.x * 8 + warp;
    const float* p = in + row * D_;
    float v[8];
    float4 a = *(const float4*)&p[lane * 8];
    float4 c = *(const float4*)&p[lane * 8 + 4];
    v[0]=a.x; v[1]=a.y; v[2]=a.z; v[3]=a.w;
    v[4]=c.x; v[5]=c.y; v[6]=c.z; v[7]=c.w;
    float sum = 0.f;
    #pragma unroll
    for (int i = 0; i < 8; i++) sum += v[i];
    #pragma unroll
    for (int off = 16; off; off >>= 1) sum += __shfl_xor_sync(0xffffffffu, sum, off);
    float mu = sum * (1.f / 256.f);
    float s2 = 0.f;
    #pragma unroll
    for (int i = 0; i < 8; i++) { float d = v[i] - mu; s2 = fmaf(d, d, s2); }
    #pragma unroll
    for (int off = 16; off; off >>= 1) s2 += __shfl_xor_sync(0xffffffffu, s2, off);
    float rs = rsqrtf(s2 * (1.f / 256.f) + 1e-5f);
    float* po = out + row * D_;
    #pragma unroll
    for (int i = 0; i < 8; i++) {
        int col = lane * 8 + i;
        float r = (v[i] - mu) * rs * gam[col] + bet[col];
        po[col] = r;
        if (oh) {
            __nv_bfloat16 hh, ll;
            split2(r, hh, ll);
            oh[row * D_ + col] = hh; ol[row * D_ + col] = ll;
        }
    }
}

// ---------------- launch ----------------
extern "C" void kernel_launch(void* const* d_in, const int* in_sizes, int n_in,
                              void* d_out, int out_size) {
    const float* x      = (const float*)d_in[0];
    const float* Wq     = (const float*)d_in[1];
    const float* Wk     = (const float*)d_in[2];
    const float* Wv     = (const float*)d_in[3];
    const float* Wproj  = (const float*)d_in[4];
    const float* bproj  = (const float*)d_in[5];
    const float* ln1_g  = (const float*)d_in[6];
    const float* ln1_b  = (const float*)d_in[7];
    const float* W1     = (const float*)d_in[8];
    const float* b1     = (const float*)d_in[9];
    const float* W2     = (const float*)d_in[10];
    const float* b2     = (const float*)d_in[11];
    const float* ln2_g  = (const float*)d_in[12];
    const float* ln2_b  = (const float*)d_in[13];
    float* out = (float*)d_out;

    float *qkvp, *y1, *ln1, *y2;
    __nv_bfloat16 *xs_h, *xs_l, *hc_h, *hc_l, *l1_h, *l1_l, *ff_h, *ff_l;
    __nv_bfloat16 *wqkv_h, *wqkv_l, *wpj_h, *wpj_l, *w1_h, *w1_l, *w2_h, *w2_l;
    cudaGetSymbolAddress((void**)&qkvp, g_qkv);
    cudaGetSymbolAddress((void**)&y1,   g_y1);
    cudaGetSymbolAddress((void**)&ln1,  g_ln1);
    cudaGetSymbolAddress((void**)&y2,   g_y2);
    cudaGetSymbolAddress((void**)&xs_h, g_xs_h); cudaGetSymbolAddress((void**)&xs_l, g_xs_l);
    cudaGetSymbolAddress((void**)&hc_h, g_hc_h); cudaGetSymbolAddress((void**)&hc_l, g_hc_l);
    cudaGetSymbolAddress((void**)&l1_h, g_l1_h); cudaGetSymbolAddress((void**)&l1_l, g_l1_l);
    cudaGetSymbolAddress((void**)&ff_h, g_ff_h); cudaGetSymbolAddress((void**)&ff_l, g_ff_l);
    cudaGetSymbolAddress((void**)&wqkv_h, g_wqkv_h); cudaGetSymbolAddress((void**)&wqkv_l, g_wqkv_l);
    cudaGetSymbolAddress((void**)&wpj_h, g_wpj_h);   cudaGetSymbolAddress((void**)&wpj_l, g_wpj_l);
    cudaGetSymbolAddress((void**)&w1_h, g_w1_h);     cudaGetSymbolAddress((void**)&w1_l, g_w1_l);
    cudaGetSymbolAddress((void**)&w2_h, g_w2_h);     cudaGetSymbolAddress((void**)&w2_l, g_w2_l);

    const int gemm_smem = 1024 + 4 * STG_BYTES;   // align slack + 4 stages = 66.5KB
    cudaFuncSetAttribute(mma_gemm<0>, cudaFuncAttributeMaxDynamicSharedMemorySize, gemm_smem);
    cudaFuncSetAttribute(mma_gemm<1>, cudaFuncAttributeMaxDynamicSharedMemorySize, gemm_smem);
    cudaFuncSetAttribute(mma_gemm<3>, cudaFuncAttributeMaxDynamicSharedMemorySize, gemm_smem);
    const int attn_smem = 2 * S_ * HS_ * (int)sizeof(float);
    cudaFuncSetAttribute(attn_kernel, cudaFuncAttributeMaxDynamicSharedMemorySize, attn_smem);

    dim3 blk(256);
    // 1) all conversions in ONE kernel
    conv_kernel<<<(CE5 + 255) / 256, blk>>>(x, Wq, Wk, Wv, Wproj, W1, W2,
                                            xs_h, xs_l, wqkv_h, wqkv_l,
                                            wpj_h, wpj_l, w1_h, w1_l, w2_h, w2_l);
    // 2) QKV: [32768,256] @ [768,256]^T -> qkv fp32
    mma_gemm<0><<<dim3(QKVP / 128, BS_ / 128), blk, gemm_smem>>>(
        xs_h, xs_l, wqkv_h, wqkv_l, nullptr, nullptr, qkvp, nullptr, nullptr, BS_, QKVP, D_);
    // 3) attention -> hc split planes
    attn_kernel<<<B_ * H_, blk, attn_smem>>>(qkvp, hc_h, hc_l);
    // 4) proj: hc @ Wproj^T + bproj + x -> y1
    mma_gemm<1><<<dim3(D_ / 128, BS_ / 128), blk, gemm_smem>>>(
        hc_h, hc_l, wpj_h, wpj_l, bproj, x, y1, nullptr, nullptr, BS_, D_, 256);
    // 5) LN1 -> ln1 fp32 + split planes
    ln_kernel<<<BS_ / 8, blk>>>(y1, ln1_g, ln1_b, ln1, l1_h, l1_l);
    // 6) FFN up: relu(ln1 @ W1^T + b1) -> ffh split planes   [ncu -s 5 lands here]
    mma_gemm<3><<<dim3(DFF_ / 128, BS_ / 128), blk, gemm_smem>>>(
        l1_h, l1_l, w1_h, w1_l, b1, nullptr, nullptr, ff_h, ff_l, BS_, DFF_, D_);
    // 7) FFN down: ffh @ W2^T + b2 + ln1 -> y2
    mma_gemm<1><<<dim3(D_ / 128, BS_ / 128), blk, gemm_smem>>>(
        ff_h, ff_l, w2_h, w2_l, b2, ln1, y2, nullptr, nullptr, BS_, D_, DFF_);
    // 8) LN2 -> out
    ln_kernel<<<BS_ / 8, blk>>>(y2, ln2_g, ln2_b, out, nullptr, nullptr);
    (void)in_sizes; (void)n_in; (void)out_size;
}